// round 2
// baseline (speedup 1.0000x reference)
#include <cuda_runtime.h>
#include <cuda_fp16.h>
#include <cstdint>
#include <cstddef>

#define Bsz 8
#define Nn  2048
#define Mm  3072
#define FEc 64
#define Dd  128

// output layout (floats): H_new, E_new, Hm, alpha, beta concatenated
#define OFF_H     ((size_t)0)
#define OFF_E     ((size_t)Bsz*Nn*Dd)                         // 2097152
#define OFF_HM    (OFF_E + (size_t)Bsz*Mm*Dd)                 // 5242880
#define OFF_ALPHA (OFF_HM + (size_t)Bsz*Nn*Dd)                // 7340032
#define OFF_BETA  (OFF_ALPHA + (size_t)Bsz*Nn*Nn)             // 40894464

// ---------------- scratch (device globals; no allocation allowed) ----------
static __device__ __half g_Eth[(size_t)Bsz*Mm*Dd];            // E_t fp16 [b][m][d]
static __device__ __half g_betaH[(size_t)Bsz*Mm*Mm];          // beta fp16
static __device__ float  g_p[Bsz*Mm];
static __device__ float  g_q[Bsz*Mm];
static __device__ float  g_mlf[Bsz*FEc];
static __device__ float  g_havg[Bsz];
static __device__ float  g_c3[Bsz];
static __device__ float  g_ec0[Bsz];
static __device__ float  g_s1, g_s2, g_b3;

// ---------------- math helpers ----------------
__device__ __forceinline__ float ex2f(float x){ float y; asm("ex2.approx.ftz.f32 %0, %1;" : "=f"(y) : "f"(x)); return y; }
__device__ __forceinline__ float rcpf(float x){ float y; asm("rcp.approx.ftz.f32 %0, %1;" : "=f"(y) : "f"(x)); return y; }
// exp(tanh(u)) : 3 MUFU + 3 FMA, ~1e-6 accurate
__device__ __forceinline__ float exp_tanh(float u){
    float w = ex2f(u * 2.8853900817779268f);     // e^{2u}
    float t = 1.f - 2.f * rcpf(1.f + w);         // tanh(u)
    return ex2f(t * 1.4426950408889634f);        // e^{tanh(u)}
}

// ---------------- K0a: per-batch stats ----------------
__global__ void stats_kernel(const float* __restrict__ bet, const float* __restrict__ lf){
    int b = blockIdx.x, tid = threadIdx.x;
    __shared__ float buf[256];
    // mean over m of link_features[b,m,f]
    float part = 0.f;
    int f = tid & 63;
    for (int m = tid >> 6; m < Mm; m += 4)
        part += lf[((size_t)b*Mm + m)*FEc + f];
    buf[tid] = part; __syncthreads();
    if (tid < 64)
        g_mlf[b*FEc + tid] = (buf[tid] + buf[tid+64] + buf[tid+128] + buf[tid+192]) * (1.f/Mm);
    // h_avg
    float hp = 0.f;
    for (int n = tid; n < Nn; n += 256) hp += bet[(size_t)b*Nn + n];
    __syncthreads();
    buf[tid] = hp; __syncthreads();
    for (int s = 128; s > 0; s >>= 1){ if (tid < s) buf[tid] += buf[tid+s]; __syncthreads(); }
    if (tid == 0) g_havg[b] = buf[0] * (1.f/Nn);
}

// ---------------- K0b: scalars ----------------
__global__ void tiny_kernel(const float* __restrict__ WH, const float* __restrict__ WE,
                            const float* __restrict__ a,  const float* __restrict__ bv){
    int tid = threadIdx.x;               // 128 threads
    __shared__ float b1s[128], b2s[128], wa3s[64], we0s[64];
    float wh = WH[tid];
    b1s[tid] = wh * a[tid];
    b2s[tid] = wh * a[128 + tid];
    __syncthreads();
    for (int s = 64; s > 0; s >>= 1){
        if (tid < s){ b1s[tid] += b1s[tid+s]; b2s[tid] += b2s[tid+s]; }
        __syncthreads();
    }
    if (tid == 0){ g_s1 = b1s[0]; g_s2 = b2s[0]; g_b3 = bv[256]; }
    if (tid < 64){
        float w3 = 0.f;
        for (int d = 0; d < Dd; d++) w3 += WE[tid*Dd + d] * a[256 + d];
        wa3s[tid] = w3; we0s[tid] = WE[tid*Dd];
    }
    __syncthreads();
    if (tid < Bsz){
        float c3 = 0.f, e0 = 0.f;
        for (int ff = 0; ff < FEc; ff++){
            float ml = g_mlf[tid*FEc + ff];
            c3 += ml * wa3s[ff]; e0 += ml * we0s[ff];
        }
        g_c3[tid] = c3; g_ec0[tid] = e0;
    }
}

// ---------------- K1: E_t (fp16) + p,q rows ----------------
__global__ void __launch_bounds__(256) et_kernel(const float* __restrict__ lf,
                                                 const float* __restrict__ WE,
                                                 const float* __restrict__ bv){
    __shared__ float4 sWE[FEc*32];       // [f][d/4]  32KB
    __shared__ float  sLF[8][FEc];       // 2KB
    int tid = threadIdx.x;
    int m0 = blockIdx.x * 8;             // global row (b*M + m)
    for (int i = tid; i < FEc*32; i += 256) sWE[i] = ((const float4*)WE)[i];
    for (int i = tid; i < 8*FEc; i += 256)
        sLF[i>>6][i&63] = lf[((size_t)(m0 + (i>>6)))*FEc + (i&63)];
    __syncthreads();
    int w = tid >> 5, lane = tid & 31;
    int gm = m0 + w;
    float ax=0.f, ay=0.f, az=0.f, aw=0.f;
    #pragma unroll
    for (int f = 0; f < FEc; f++){
        float lv = sLF[w][f];
        float4 wv = sWE[f*32 + lane];
        ax = fmaf(lv, wv.x, ax); ay = fmaf(lv, wv.y, ay);
        az = fmaf(lv, wv.z, az); aw = fmaf(lv, wv.w, aw);
    }
    int d0 = lane * 4;
    float pp = ax*bv[d0] + ay*bv[d0+1] + az*bv[d0+2] + aw*bv[d0+3];
    float qq = ax*bv[128+d0] + ay*bv[128+d0+1] + az*bv[128+d0+2] + aw*bv[128+d0+3];
    #pragma unroll
    for (int o = 16; o; o >>= 1){
        pp += __shfl_xor_sync(0xffffffffu, pp, o);
        qq += __shfl_xor_sync(0xffffffffu, qq, o);
    }
    if (lane == 0){ g_p[gm] = pp; g_q[gm] = qq; }
    __half2* eh = (__half2*)g_Eth;
    eh[(size_t)gm*64 + lane*2]     = __floats2half2_rn(ax, ay);
    eh[(size_t)gm*64 + lane*2 + 1] = __floats2half2_rn(az, aw);
}

// ---------------- K2: alpha + H_new + Hm ----------------
__global__ void __launch_bounds__(256) alpha_kernel(const float* __restrict__ bet,
                                                    const int* __restrict__ adj,
                                                    const float* __restrict__ WH,
                                                    float* __restrict__ out){
    __shared__ float rowbuf[Nn];
    __shared__ float red[2][8];
    __shared__ float sc[2];
    int gi = blockIdx.x;                 // b*N + i
    int b = gi >> 11;
    int tid = threadIdx.x;
    float s2 = g_s2;
    float c = bet[gi] * g_s1 + g_c3[b];
    const int*   arow = adj + (size_t)gi * Nn;
    const float* brow = bet + (size_t)b * Nn;
    float lsum = 0.f, lw = 0.f;
    #pragma unroll
    for (int j = tid; j < Nn; j += 256){
        float bj = brow[j];
        float v = 0.f;
        if (arow[j] > 0) v = exp_tanh(fmaf(s2, bj, c));
        rowbuf[j] = v; lsum += v; lw = fmaf(v, bj, lw);
    }
    #pragma unroll
    for (int o = 16; o; o >>= 1){
        lsum += __shfl_xor_sync(0xffffffffu, lsum, o);
        lw   += __shfl_xor_sync(0xffffffffu, lw, o);
    }
    int wid = tid >> 5;
    if ((tid & 31) == 0){ red[0][wid] = lsum; red[1][wid] = lw; }
    __syncthreads();
    if (tid == 0){
        float s = 0.f, wv = 0.f;
        #pragma unroll
        for (int k = 0; k < 8; k++){ s += red[0][k]; wv += red[1][k]; }
        if (s > 0.f){ sc[0] = 1.f/s; sc[1] = wv/s; }
        else        { sc[0] = -1.f;  sc[1] = g_havg[b]; }   // fully-masked row
    }
    __syncthreads();
    float inv = sc[0];
    float* ao = out + OFF_ALPHA + (size_t)gi * Nn;
    if (inv > 0.f){
        #pragma unroll
        for (int j = tid; j < Nn; j += 256) ao[j] = rowbuf[j] * inv;
    } else {
        #pragma unroll
        for (int j = tid; j < Nn; j += 256) ao[j] = 1.f/Nn;
    }
    if (tid < Dd){
        float h = sc[1] * WH[tid];
        out[OFF_H  + (size_t)gi*Dd + tid] = h;
        out[OFF_HM + (size_t)gi*Dd + tid] = g_ec0[b] * h;
    }
}

// ---------------- K3: beta (fp32 out + fp16 scratch) ----------------
__global__ void __launch_bounds__(256) beta_kernel(const int* __restrict__ adj,
                                                   float* __restrict__ out){
    __shared__ float rowbuf[Mm];
    __shared__ float red[8];
    __shared__ float sinv;
    int gi = blockIdx.x;                 // b*M + i
    int b = gi / Mm;
    int tid = threadIdx.x;
    float c = g_p[gi] + g_b3 * g_havg[b];
    const int*   arow = adj + (size_t)gi * Mm;
    const float* qrow = g_q + (size_t)b * Mm;
    float lsum = 0.f;
    #pragma unroll
    for (int j = tid; j < Mm; j += 256){
        float v = 0.f;
        if (arow[j] > 0) v = exp_tanh(c + qrow[j]);
        rowbuf[j] = v; lsum += v;
    }
    #pragma unroll
    for (int o = 16; o; o >>= 1) lsum += __shfl_xor_sync(0xffffffffu, lsum, o);
    if ((tid & 31) == 0) red[tid >> 5] = lsum;
    __syncthreads();
    if (tid == 0){
        float s = 0.f;
        #pragma unroll
        for (int k = 0; k < 8; k++) s += red[k];
        sinv = (s > 0.f) ? 1.f/s : -1.f;
    }
    __syncthreads();
    float inv = sinv;
    float*  bo = out + OFF_BETA + (size_t)gi * Mm;
    __half* bh = g_betaH + (size_t)gi * Mm;
    if (inv > 0.f){
        #pragma unroll
        for (int j = tid; j < Mm; j += 256){
            float v = rowbuf[j] * inv; bo[j] = v; bh[j] = __float2half_rn(v);
        }
    } else {
        float v = 1.f/Mm;
        #pragma unroll
        for (int j = tid; j < Mm; j += 256){ bo[j] = v; bh[j] = __float2half_rn(v); }
    }
}

// ---------------- K4: E_new = beta @ E_t   (fp16 mma.sync, fp32 accum) -----
__device__ __forceinline__ void cp16(void* d, const void* s){
    uint32_t ds = (uint32_t)__cvta_generic_to_shared(d);
    asm volatile("cp.async.cg.shared.global [%0], [%1], 16;" :: "r"(ds), "l"(s));
}
__device__ __forceinline__ void ldm_x4(uint32_t* r, uint32_t a){
    asm volatile("ldmatrix.sync.aligned.m8n8.x4.shared.b16 {%0,%1,%2,%3}, [%4];"
        : "=r"(r[0]), "=r"(r[1]), "=r"(r[2]), "=r"(r[3]) : "r"(a));
}
__device__ __forceinline__ void ldm_x4_t(uint32_t* r, uint32_t a){
    asm volatile("ldmatrix.sync.aligned.m8n8.x4.trans.shared.b16 {%0,%1,%2,%3}, [%4];"
        : "=r"(r[0]), "=r"(r[1]), "=r"(r[2]), "=r"(r[3]) : "r"(a));
}
__device__ __forceinline__ void mma16816(float* c, const uint32_t* a, const uint32_t* bq){
    asm volatile("mma.sync.aligned.m16n8k16.row.col.f32.f16.f16.f32 "
        "{%0,%1,%2,%3}, {%4,%5,%6,%7}, {%8,%9}, {%0,%1,%2,%3};"
        : "+f"(c[0]), "+f"(c[1]), "+f"(c[2]), "+f"(c[3])
        : "r"(a[0]), "r"(a[1]), "r"(a[2]), "r"(a[3]), "r"(bq[0]), "r"(bq[1]));
}

#define KSTEP 32
#define NKIT  (Mm / KSTEP)   // 96

__global__ void __launch_bounds__(256) enew_kernel(float* __restrict__ out){
    __shared__ __align__(16) __half As[2][64][40];    // 32 + row-pad 8
    __shared__ __align__(16) __half Bs[2][KSTEP][136];// 128 + pad 8
    int tid = threadIdx.x;
    int b  = blockIdx.y;
    int i0 = blockIdx.x * 64;
    const __half* Ab = g_betaH + (size_t)b*Mm*Mm + (size_t)i0*Mm;
    const __half* Bb = g_Eth   + (size_t)b*Mm*Dd;

    auto load_stage = [&](int kt, int st){
        int k0 = kt * KSTEP;
        {   // A: 64 rows x 64B -> 256 chunks
            int row = tid >> 2, c = tid & 3;
            cp16(&As[st][row][c*8], Ab + (size_t)row*Mm + k0 + c*8);
        }
        #pragma unroll
        for (int t = 0; t < 2; t++){   // B: 32 rows x 256B -> 512 chunks
            int ch = tid + t*256;
            int row = ch >> 4, c = ch & 15;
            cp16(&Bs[st][row][c*8], Bb + (size_t)(k0 + row)*Dd + c*8);
        }
        asm volatile("cp.async.commit_group;");
    };

    int lane = tid & 31, wid = tid >> 5;
    int wm = wid & 1, wn = wid >> 1;     // warp tile 32(m) x 32(n)
    float acc[2][4][4] = {};

    load_stage(0, 0);
    for (int kt = 0; kt < NKIT; kt++){
        if (kt + 1 < NKIT){
            load_stage(kt + 1, (kt + 1) & 1);
            asm volatile("cp.async.wait_group 1;");
        } else {
            asm volatile("cp.async.wait_group 0;");
        }
        __syncthreads();
        int st = kt & 1;
        #pragma unroll
        for (int ks = 0; ks < 2; ks++){
            uint32_t ra[2][4], rb[4][2];
            #pragma unroll
            for (int am = 0; am < 2; am++){
                const __half* ap = &As[st][wm*32 + am*16 + (lane & 15)][ks*16 + ((lane >> 4) << 3)];
                ldm_x4(ra[am], (uint32_t)__cvta_generic_to_shared(ap));
            }
            #pragma unroll
            for (int nb = 0; nb < 2; nb++){
                uint32_t r4[4];
                const __half* bp = &Bs[st][ks*16 + (lane & 15)][wn*32 + nb*16 + ((lane >> 4) << 3)];
                ldm_x4_t(r4, (uint32_t)__cvta_generic_to_shared(bp));
                rb[nb*2][0] = r4[0]; rb[nb*2][1] = r4[1];
                rb[nb*2+1][0] = r4[2]; rb[nb*2+1][1] = r4[3];
            }
            #pragma unroll
            for (int am = 0; am < 2; am++)
                #pragma unroll
                for (int nn = 0; nn < 4; nn++)
                    mma16816(acc[am][nn], ra[am], rb[nn]);
        }
        __syncthreads();
    }
    // epilogue: fp32 direct to out
    float* Eo = out + OFF_E + ((size_t)b*Mm + i0) * Dd;
    #pragma unroll
    for (int am = 0; am < 2; am++){
        #pragma unroll
        for (int nn = 0; nn < 4; nn++){
            int r0 = wm*32 + am*16 + (lane >> 2);
            int c0 = wn*32 + nn*8 + (lane & 3)*2;
            *(float2*)(Eo + (size_t)r0*Dd + c0)       = make_float2(acc[am][nn][0], acc[am][nn][1]);
            *(float2*)(Eo + (size_t)(r0+8)*Dd + c0)   = make_float2(acc[am][nn][2], acc[am][nn][3]);
        }
    }
}

// ---------------- launch ----------------
extern "C" void kernel_launch(void* const* d_in, const int* in_sizes, int n_in,
                              void* d_out, int out_size){
    (void)in_sizes; (void)n_in; (void)out_size;
    const float* bet = (const float*)d_in[0];
    const float* lf  = (const float*)d_in[1];
    const int*   nadj= (const int*)  d_in[2];
    const int*   eadj= (const int*)  d_in[3];
    const float* WH  = (const float*)d_in[4];
    const float* WE  = (const float*)d_in[5];
    const float* a   = (const float*)d_in[6];
    const float* bv  = (const float*)d_in[7];
    float* out = (float*)d_out;

    stats_kernel<<<Bsz, 256>>>(bet, lf);
    tiny_kernel<<<1, 128>>>(WH, WE, a, bv);
    et_kernel<<<Bsz*Mm/8, 256>>>(lf, WE, bv);
    alpha_kernel<<<Bsz*Nn, 256>>>(bet, nadj, WH, out);
    beta_kernel<<<Bsz*Mm, 256>>>(eadj, out);
    enew_kernel<<<dim3(Mm/64, Bsz), 256>>>(out);
}

// round 3
// speedup vs baseline: 1.0185x; 1.0185x over previous
#include <cuda_runtime.h>
#include <cuda_fp16.h>
#include <cstdint>
#include <cstddef>

#define Bsz 8
#define Nn  2048
#define Mm  3072
#define FEc 64
#define Dd  128

// output layout (floats): H_new, E_new, Hm, alpha, beta concatenated
#define OFF_H     ((size_t)0)
#define OFF_E     ((size_t)Bsz*Nn*Dd)                         // 2097152
#define OFF_HM    (OFF_E + (size_t)Bsz*Mm*Dd)                 // 5242880
#define OFF_ALPHA (OFF_HM + (size_t)Bsz*Nn*Dd)                // 7340032
#define OFF_BETA  (OFF_ALPHA + (size_t)Bsz*Nn*Nn)             // 40894464

// ---------------- scratch (device globals; no allocation allowed) ----------
static __device__ __half g_Eth[(size_t)Bsz*Mm*Dd];            // E_t fp16 [b][m][d]
static __device__ float  g_p[Bsz*Mm];
static __device__ float  g_q[Bsz*Mm];
static __device__ float  g_mlf[Bsz*FEc];
static __device__ float  g_havg[Bsz];
static __device__ float  g_c3[Bsz];
static __device__ float  g_ec0[Bsz];
static __device__ float  g_s1, g_s2, g_b3;

// ---------------- math helpers ----------------
__device__ __forceinline__ float ex2f(float x){ float y; asm("ex2.approx.ftz.f32 %0, %1;" : "=f"(y) : "f"(x)); return y; }
__device__ __forceinline__ float rcpf(float x){ float y; asm("rcp.approx.ftz.f32 %0, %1;" : "=f"(y) : "f"(x)); return y; }
// exp(tanh(u)) : 3 MUFU + 3 FMA, ~1e-6 accurate
__device__ __forceinline__ float exp_tanh(float u){
    float w = ex2f(u * 2.8853900817779268f);     // e^{2u}
    float t = 1.f - 2.f * rcpf(1.f + w);         // tanh(u)
    return ex2f(t * 1.4426950408889634f);        // e^{tanh(u)}
}

// ---------------- K0a: per-batch stats ----------------
__global__ void stats_kernel(const float* __restrict__ bet, const float* __restrict__ lf){
    int b = blockIdx.x, tid = threadIdx.x;
    __shared__ float buf[256];
    float part = 0.f;
    int f = tid & 63;
    for (int m = tid >> 6; m < Mm; m += 4)
        part += lf[((size_t)b*Mm + m)*FEc + f];
    buf[tid] = part; __syncthreads();
    if (tid < 64)
        g_mlf[b*FEc + tid] = (buf[tid] + buf[tid+64] + buf[tid+128] + buf[tid+192]) * (1.f/Mm);
    float hp = 0.f;
    for (int n = tid; n < Nn; n += 256) hp += bet[(size_t)b*Nn + n];
    __syncthreads();
    buf[tid] = hp; __syncthreads();
    for (int s = 128; s > 0; s >>= 1){ if (tid < s) buf[tid] += buf[tid+s]; __syncthreads(); }
    if (tid == 0) g_havg[b] = buf[0] * (1.f/Nn);
}

// ---------------- K0b: scalars ----------------
__global__ void tiny_kernel(const float* __restrict__ WH, const float* __restrict__ WE,
                            const float* __restrict__ a,  const float* __restrict__ bv){
    int tid = threadIdx.x;               // 128 threads
    __shared__ float b1s[128], b2s[128], wa3s[64], we0s[64];
    float wh = WH[tid];
    b1s[tid] = wh * a[tid];
    b2s[tid] = wh * a[128 + tid];
    __syncthreads();
    for (int s = 64; s > 0; s >>= 1){
        if (tid < s){ b1s[tid] += b1s[tid+s]; b2s[tid] += b2s[tid+s]; }
        __syncthreads();
    }
    if (tid == 0){ g_s1 = b1s[0]; g_s2 = b2s[0]; g_b3 = bv[256]; }
    if (tid < 64){
        float w3 = 0.f;
        for (int d = 0; d < Dd; d++) w3 += WE[tid*Dd + d] * a[256 + d];
        wa3s[tid] = w3; we0s[tid] = WE[tid*Dd];
    }
    __syncthreads();
    if (tid < Bsz){
        float c3 = 0.f, e0 = 0.f;
        for (int ff = 0; ff < FEc; ff++){
            float ml = g_mlf[tid*FEc + ff];
            c3 += ml * wa3s[ff]; e0 += ml * we0s[ff];
        }
        g_c3[tid] = c3; g_ec0[tid] = e0;
    }
}

// ---------------- K1: E_t (fp16) + p,q rows ----------------
__global__ void __launch_bounds__(256) et_kernel(const float* __restrict__ lf,
                                                 const float* __restrict__ WE,
                                                 const float* __restrict__ bv){
    __shared__ float4 sWE[FEc*32];       // [f][d/4]  32KB
    __shared__ float  sLF[8][FEc];       // 2KB
    int tid = threadIdx.x;
    int m0 = blockIdx.x * 8;             // global row (b*M + m)
    for (int i = tid; i < FEc*32; i += 256) sWE[i] = ((const float4*)WE)[i];
    for (int i = tid; i < 8*FEc; i += 256)
        sLF[i>>6][i&63] = lf[((size_t)(m0 + (i>>6)))*FEc + (i&63)];
    __syncthreads();
    int w = tid >> 5, lane = tid & 31;
    int gm = m0 + w;
    float ax=0.f, ay=0.f, az=0.f, aw=0.f;
    #pragma unroll
    for (int f = 0; f < FEc; f++){
        float lv = sLF[w][f];
        float4 wv = sWE[f*32 + lane];
        ax = fmaf(lv, wv.x, ax); ay = fmaf(lv, wv.y, ay);
        az = fmaf(lv, wv.z, az); aw = fmaf(lv, wv.w, aw);
    }
    int d0 = lane * 4;
    float pp = ax*bv[d0] + ay*bv[d0+1] + az*bv[d0+2] + aw*bv[d0+3];
    float qq = ax*bv[128+d0] + ay*bv[128+d0+1] + az*bv[128+d0+2] + aw*bv[128+d0+3];
    #pragma unroll
    for (int o = 16; o; o >>= 1){
        pp += __shfl_xor_sync(0xffffffffu, pp, o);
        qq += __shfl_xor_sync(0xffffffffu, qq, o);
    }
    if (lane == 0){ g_p[gm] = pp; g_q[gm] = qq; }
    __half2* eh = (__half2*)g_Eth;
    eh[(size_t)gm*64 + lane*2]     = __floats2half2_rn(ax, ay);
    eh[(size_t)gm*64 + lane*2 + 1] = __floats2half2_rn(az, aw);
}

// ---------------- K2: alpha + H_new + Hm  (vectorized int4/float4) --------
__global__ void __launch_bounds__(256) alpha_kernel(const float* __restrict__ bet,
                                                    const int* __restrict__ adj,
                                                    const float* __restrict__ WH,
                                                    float* __restrict__ out){
    __shared__ float4 rowbuf[Nn/4];      // 8KB
    __shared__ float red[2][8];
    __shared__ float sc[2];
    int gi = blockIdx.x;                 // b*N + i
    int b = gi >> 11;
    int tid = threadIdx.x;
    float s2 = g_s2;
    float c = bet[gi] * g_s1 + g_c3[b];
    const int4*   arow = (const int4*)(adj + (size_t)gi * Nn);
    const float4* brow = (const float4*)(bet + (size_t)b * Nn);
    float lsum = 0.f, lw = 0.f;
    #pragma unroll
    for (int j = tid; j < Nn/4; j += 256){
        int4   a4 = arow[j];
        float4 b4 = brow[j];
        float4 v;
        v.x = (a4.x > 0) ? exp_tanh(fmaf(s2, b4.x, c)) : 0.f;
        v.y = (a4.y > 0) ? exp_tanh(fmaf(s2, b4.y, c)) : 0.f;
        v.z = (a4.z > 0) ? exp_tanh(fmaf(s2, b4.z, c)) : 0.f;
        v.w = (a4.w > 0) ? exp_tanh(fmaf(s2, b4.w, c)) : 0.f;
        rowbuf[j] = v;
        lsum += (v.x + v.y) + (v.z + v.w);
        lw = fmaf(v.x, b4.x, fmaf(v.y, b4.y, fmaf(v.z, b4.z, fmaf(v.w, b4.w, lw))));
    }
    #pragma unroll
    for (int o = 16; o; o >>= 1){
        lsum += __shfl_xor_sync(0xffffffffu, lsum, o);
        lw   += __shfl_xor_sync(0xffffffffu, lw, o);
    }
    int wid = tid >> 5;
    if ((tid & 31) == 0){ red[0][wid] = lsum; red[1][wid] = lw; }
    __syncthreads();
    if (tid == 0){
        float s = 0.f, wv = 0.f;
        #pragma unroll
        for (int k = 0; k < 8; k++){ s += red[0][k]; wv += red[1][k]; }
        if (s > 0.f){ sc[0] = 1.f/s; sc[1] = wv/s; }
        else        { sc[0] = -1.f;  sc[1] = g_havg[b]; }   // fully-masked row
    }
    __syncthreads();
    float inv = sc[0];
    float4* ao = (float4*)(out + OFF_ALPHA + (size_t)gi * Nn);
    if (inv > 0.f){
        #pragma unroll
        for (int j = tid; j < Nn/4; j += 256){
            float4 v = rowbuf[j];
            ao[j] = make_float4(v.x*inv, v.y*inv, v.z*inv, v.w*inv);
        }
    } else {
        float4 u = make_float4(1.f/Nn, 1.f/Nn, 1.f/Nn, 1.f/Nn);
        #pragma unroll
        for (int j = tid; j < Nn/4; j += 256) ao[j] = u;
    }
    if (tid < Dd){
        float h = sc[1] * WH[tid];
        out[OFF_H  + (size_t)gi*Dd + tid] = h;
        out[OFF_HM + (size_t)gi*Dd + tid] = g_ec0[b] * h;
    }
}

// ---------------- K3: beta (fp32 out only, vectorized) --------------------
__global__ void __launch_bounds__(256) beta_kernel(const int* __restrict__ adj,
                                                   float* __restrict__ out){
    __shared__ float4 rowbuf[Mm/4];      // 12KB
    __shared__ float red[8];
    __shared__ float sinv;
    int gi = blockIdx.x;                 // b*M + i
    int b = (int)((unsigned)gi / Mm);
    int tid = threadIdx.x;
    float c = g_p[gi] + g_b3 * g_havg[b];
    const int4*   arow = (const int4*)(adj + (size_t)gi * Mm);
    const float4* qrow = (const float4*)(g_q + (size_t)b * Mm);
    float lsum = 0.f;
    #pragma unroll
    for (int j = tid; j < Mm/4; j += 256){
        int4   a4 = arow[j];
        float4 q4 = qrow[j];
        float4 v;
        v.x = (a4.x > 0) ? exp_tanh(c + q4.x) : 0.f;
        v.y = (a4.y > 0) ? exp_tanh(c + q4.y) : 0.f;
        v.z = (a4.z > 0) ? exp_tanh(c + q4.z) : 0.f;
        v.w = (a4.w > 0) ? exp_tanh(c + q4.w) : 0.f;
        rowbuf[j] = v;
        lsum += (v.x + v.y) + (v.z + v.w);
    }
    #pragma unroll
    for (int o = 16; o; o >>= 1) lsum += __shfl_xor_sync(0xffffffffu, lsum, o);
    if ((tid & 31) == 0) red[tid >> 5] = lsum;
    __syncthreads();
    if (tid == 0){
        float s = 0.f;
        #pragma unroll
        for (int k = 0; k < 8; k++) s += red[k];
        sinv = (s > 0.f) ? 1.f/s : -1.f;
    }
    __syncthreads();
    float inv = sinv;
    float4* bo = (float4*)(out + OFF_BETA + (size_t)gi * Mm);
    if (inv > 0.f){
        #pragma unroll
        for (int j = tid; j < Mm/4; j += 256){
            float4 v = rowbuf[j];
            bo[j] = make_float4(v.x*inv, v.y*inv, v.z*inv, v.w*inv);
        }
    } else {
        float4 u = make_float4(1.f/Mm, 1.f/Mm, 1.f/Mm, 1.f/Mm);
        #pragma unroll
        for (int j = tid; j < Mm/4; j += 256) bo[j] = u;
    }
}

// ---------------- K4: E_new = beta @ E_t   (fp16 mma.sync, fp32 accum) -----
// A (beta) is read as fp32 from the output buffer, converted to fp16 in regs.
__device__ __forceinline__ void cp16(void* d, const void* s){
    uint32_t ds = (uint32_t)__cvta_generic_to_shared(d);
    asm volatile("cp.async.cg.shared.global [%0], [%1], 16;" :: "r"(ds), "l"(s));
}
__device__ __forceinline__ void ldm_x4(uint32_t* r, uint32_t a){
    asm volatile("ldmatrix.sync.aligned.m8n8.x4.shared.b16 {%0,%1,%2,%3}, [%4];"
        : "=r"(r[0]), "=r"(r[1]), "=r"(r[2]), "=r"(r[3]) : "r"(a));
}
__device__ __forceinline__ void ldm_x4_t(uint32_t* r, uint32_t a){
    asm volatile("ldmatrix.sync.aligned.m8n8.x4.trans.shared.b16 {%0,%1,%2,%3}, [%4];"
        : "=r"(r[0]), "=r"(r[1]), "=r"(r[2]), "=r"(r[3]) : "r"(a));
}
__device__ __forceinline__ void mma16816(float* c, const uint32_t* a, const uint32_t* bq){
    asm volatile("mma.sync.aligned.m16n8k16.row.col.f32.f16.f16.f32 "
        "{%0,%1,%2,%3}, {%4,%5,%6,%7}, {%8,%9}, {%0,%1,%2,%3};"
        : "+f"(c[0]), "+f"(c[1]), "+f"(c[2]), "+f"(c[3])
        : "r"(a[0]), "r"(a[1]), "r"(a[2]), "r"(a[3]), "r"(bq[0]), "r"(bq[1]));
}

#define KSTEP 32
#define NKIT  (Mm / KSTEP)   // 96

__global__ void __launch_bounds__(256) enew_kernel(float* __restrict__ out){
    __shared__ __align__(16) __half As[2][64][40];    // 32 + row-pad 8
    __shared__ __align__(16) __half Bs[2][KSTEP][136];// 128 + pad 8
    int tid = threadIdx.x;
    int b  = blockIdx.y;
    int i0 = blockIdx.x * 64;
    const float* Ab = out + OFF_BETA + ((size_t)b*Mm + i0) * Mm;   // fp32 beta
    const __half* Bb = g_Eth + (size_t)b*Mm*Dd;

    int arow = tid >> 2, acol = (tid & 3) * 8;        // per-thread A slot
    const float* Abase = Ab + (size_t)arow * Mm + acol;

    auto ldgA = [&](int kt, float4& v0, float4& v1){
        const float4* p = (const float4*)(Abase + kt * KSTEP);
        v0 = __ldg(p); v1 = __ldg(p + 1);
    };
    auto stsA = [&](int st, float4 v0, float4 v1){
        __half2 h[4];
        h[0] = __floats2half2_rn(v0.x, v0.y); h[1] = __floats2half2_rn(v0.z, v0.w);
        h[2] = __floats2half2_rn(v1.x, v1.y); h[3] = __floats2half2_rn(v1.z, v1.w);
        *(uint4*)&As[st][arow][acol] = *(uint4*)h;
    };
    auto ldB = [&](int kt, int st){
        int k0 = kt * KSTEP;
        #pragma unroll
        for (int t = 0; t < 2; t++){   // B: 32 rows x 256B -> 512 chunks
            int ch = tid + t*256;
            int row = ch >> 4, c = ch & 15;
            cp16(&Bs[st][row][c*8], Bb + (size_t)(k0 + row)*Dd + c*8);
        }
        asm volatile("cp.async.commit_group;");
    };

    int lane = tid & 31, wid = tid >> 5;
    int wm = wid & 1, wn = wid >> 1;     // warp tile 32(m) x 32(n)
    float acc[2][4][4] = {};

    float4 a0, a1, na0, na1;
    ldgA(0, a0, a1);
    ldB(0, 0);
    for (int kt = 0; kt < NKIT; kt++){
        int st = kt & 1;
        stsA(st, a0, a1);
        if (kt + 1 < NKIT){
            ldgA(kt + 1, na0, na1);
            ldB(kt + 1, st ^ 1);
            asm volatile("cp.async.wait_group 1;");
        } else {
            asm volatile("cp.async.wait_group 0;");
        }
        __syncthreads();
        #pragma unroll
        for (int ks = 0; ks < 2; ks++){
            uint32_t ra[2][4], rb[4][2];
            #pragma unroll
            for (int am = 0; am < 2; am++){
                const __half* ap = &As[st][wm*32 + am*16 + (lane & 15)][ks*16 + ((lane >> 4) << 3)];
                ldm_x4(ra[am], (uint32_t)__cvta_generic_to_shared(ap));
            }
            #pragma unroll
            for (int nb = 0; nb < 2; nb++){
                uint32_t r4[4];
                const __half* bp = &Bs[st][ks*16 + (lane & 15)][wn*32 + nb*16 + ((lane >> 4) << 3)];
                ldm_x4_t(r4, (uint32_t)__cvta_generic_to_shared(bp));
                rb[nb*2][0] = r4[0]; rb[nb*2][1] = r4[1];
                rb[nb*2+1][0] = r4[2]; rb[nb*2+1][1] = r4[3];
            }
            #pragma unroll
            for (int am = 0; am < 2; am++)
                #pragma unroll
                for (int nn = 0; nn < 4; nn++)
                    mma16816(acc[am][nn], ra[am], rb[nn]);
        }
        __syncthreads();
        a0 = na0; a1 = na1;
    }
    // epilogue: fp32 direct to out
    float* Eo = out + OFF_E + ((size_t)b*Mm + i0) * Dd;
    #pragma unroll
    for (int am = 0; am < 2; am++){
        #pragma unroll
        for (int nn = 0; nn < 4; nn++){
            int r0 = wm*32 + am*16 + (lane >> 2);
            int c0 = wn*32 + nn*8 + (lane & 3)*2;
            *(float2*)(Eo + (size_t)r0*Dd + c0)       = make_float2(acc[am][nn][0], acc[am][nn][1]);
            *(float2*)(Eo + (size_t)(r0+8)*Dd + c0)   = make_float2(acc[am][nn][2], acc[am][nn][3]);
        }
    }
}

// ---------------- launch ----------------
extern "C" void kernel_launch(void* const* d_in, const int* in_sizes, int n_in,
                              void* d_out, int out_size){
    (void)in_sizes; (void)n_in; (void)out_size;
    const float* bet = (const float*)d_in[0];
    const float* lf  = (const float*)d_in[1];
    const int*   nadj= (const int*)  d_in[2];
    const int*   eadj= (const int*)  d_in[3];
    const float* WH  = (const float*)d_in[4];
    const float* WE  = (const float*)d_in[5];
    const float* a   = (const float*)d_in[6];
    const float* bv  = (const float*)d_in[7];
    float* out = (float*)d_out;

    stats_kernel<<<Bsz, 256>>>(bet, lf);
    tiny_kernel<<<1, 128>>>(WH, WE, a, bv);
    et_kernel<<<Bsz*Mm/8, 256>>>(lf, WE, bv);
    beta_kernel<<<Bsz*Mm, 256>>>(eadj, out);
    enew_kernel<<<dim3(Mm/64, Bsz), 256>>>(out);
    alpha_kernel<<<Bsz*Nn, 256>>>(bet, nadj, WH, out);
}